// round 1
// baseline (speedup 1.0000x reference)
#include <cuda_runtime.h>
#include <math.h>

#define T_   2048
#define BK   64
#define H_   16
#define N_   64
#define OBS_ 64
#define TB   (T_*BK)        // 131072 rows
#define NCOL 144            // 64 (B) + 64 (C) + 16 (s0 per head)
#define PROJ_SMEM (64*NCOL*4 + 64*65*4)   // 53504 bytes

// -------- device scratch (static, no allocations in kernel_launch) --------
__device__ float  g_Bm[(size_t)TB*N_];      // 33.5 MB  B_t[b][n]
__device__ float  g_Cm[(size_t)TB*N_];      // 33.5 MB  C_t[b][n]
__device__ float4 g_sdu[(size_t)TB*H_];     // 33.5 MB  (s, dec, du, 0) per (t,b,h)
__device__ float  g_part[(size_t)TB*H_];    // 8 MB     per-head output partials
__device__ float  g_V[OBS_*H_];             // folded W_in @ blockdiag(W_out)
__device__ float  g_g0[H_*N_];              // folded init_state @ W_out

// ---------------------------------------------------------------------------
// prep: V[o,h] = sum_p W_in[o, h*64+p] * W_out[h*64+p]
//       g0[h,n] = sum_p init[h,p,n] * W_out[h*64+p]
// ---------------------------------------------------------------------------
__global__ void prep_kernel(const float* __restrict__ W_in,
                            const float* __restrict__ W_out,
                            const float* __restrict__ init_state) {
    int tid = blockIdx.x * blockDim.x + threadIdx.x;
    if (tid < OBS_ * H_) {
        int o = tid >> 4, h = tid & 15;
        float acc = 0.f;
        #pragma unroll 8
        for (int p = 0; p < 64; p++)
            acc = fmaf(W_in[o*1024 + h*64 + p], W_out[h*64 + p], acc);
        g_V[o*H_ + h] = acc;
    } else if (tid < OBS_*H_ + H_*N_) {
        int i = tid - OBS_*H_;
        int h = i >> 6, n = i & 63;
        float acc = 0.f;
        #pragma unroll 8
        for (int p = 0; p < 64; p++)
            acc = fmaf(init_state[(h*64 + p)*64 + n], W_out[h*64 + p], acc);
        g_g0[i] = acc;
    }
}

// ---------------------------------------------------------------------------
// proj: rows = (t*BK+b), GEMM obs(row,64) @ [W_B | W_C | V](64,144)
// epilogue for cols 128..143: dt = softplus(reward*W_dt + bias),
//   dec = exp(dt*(-exp(A_log))), s = dt*s0, du = D*s0
// tile: 64 rows x 144 cols per block, 256 threads = 16x16, each 4 rows x 9 cols
// ---------------------------------------------------------------------------
__global__ void proj_kernel(const float* __restrict__ obs,
                            const float* __restrict__ reward,
                            const float* __restrict__ W_B,
                            const float* __restrict__ W_C,
                            const float* __restrict__ W_dt,
                            const float* __restrict__ dt_bias,
                            const float* __restrict__ A_log,
                            const float* __restrict__ Dv) {
    extern __shared__ float sm[];
    float* sW = sm;               // [64][144]
    float* sO = sm + 64*NCOL;     // [64][65] padded

    int tid = threadIdx.x;
    for (int i = tid; i < 64*NCOL; i += 256) {
        int k = i / NCOL, c = i - k*NCOL;
        float v;
        if (c < 64)       v = W_B[k*64 + c];
        else if (c < 128) v = W_C[k*64 + c - 64];
        else              v = g_V[k*16 + c - 128];
        sW[i] = v;
    }
    int row0 = blockIdx.x * 64;
    for (int i = tid; i < 1024; i += 256) {          // 64 rows * 16 float4
        int r = i >> 4, c4 = i & 15;
        float4 v = *(const float4*)(obs + (size_t)(row0 + r)*64 + c4*4);
        float* d = sO + r*65 + c4*4;
        d[0] = v.x; d[1] = v.y; d[2] = v.z; d[3] = v.w;
    }
    __syncthreads();

    int ty = tid >> 4, tx = tid & 15;
    float acc[4][9];
    #pragma unroll
    for (int i = 0; i < 4; i++)
        #pragma unroll
        for (int j = 0; j < 9; j++) acc[i][j] = 0.f;

    #pragma unroll 4
    for (int k = 0; k < 64; k++) {
        float a[4], bb[9];
        #pragma unroll
        for (int i = 0; i < 4; i++) a[i] = sO[(ty + 16*i)*65 + k];
        #pragma unroll
        for (int j = 0; j < 9; j++) bb[j] = sW[k*NCOL + tx*9 + j];
        #pragma unroll
        for (int i = 0; i < 4; i++)
            #pragma unroll
            for (int j = 0; j < 9; j++)
                acc[i][j] = fmaf(a[i], bb[j], acc[i][j]);
    }

    #pragma unroll
    for (int i = 0; i < 4; i++) {
        int row = row0 + ty + 16*i;
        #pragma unroll
        for (int j = 0; j < 9; j++) {
            int c = tx*9 + j;
            float v = acc[i][j];
            if (c < 64) {
                g_Bm[(size_t)row*64 + c] = v;
            } else if (c < 128) {
                g_Cm[(size_t)row*64 + c - 64] = v;
            } else {
                int h = c - 128;
                float x   = fmaf(reward[row], W_dt[h], dt_bias[h]);
                float dtv = fmaxf(x, 0.f) + log1pf(expf(-fabsf(x)));   // softplus
                float A   = -expf(A_log[h]);
                float dec = expf(dtv * A);
                g_sdu[(size_t)row*16 + h] = make_float4(dtv * v, dec, Dv[h] * v, 0.f);
            }
        }
    }
}

// ---------------------------------------------------------------------------
// scan: 128 CTAs x 256 threads. CTA = (b, head-octet). Warp w = one head.
// lane owns states n = {lane, lane+32}. B/C/sdu staged in smem in
// double-buffered batches of 8 timesteps; global loads issued 1 batch ahead.
// ---------------------------------------------------------------------------
__global__ void scan_kernel() {
    __shared__ float  sB[2][8][64];
    __shared__ float  sC[2][8][64];
    __shared__ float4 sS[2][8][16];

    int b    = blockIdx.x >> 1;
    int hg   = blockIdx.x & 1;
    int tid  = threadIdx.x;
    int w    = tid >> 5;
    int lane = tid & 31;
    int h    = hg*8 + w;

    float g1 = g_g0[h*64 + lane];
    float g2 = g_g0[h*64 + lane + 32];

    int tt = tid >> 5;    // timestep slot within batch (0..7)
    int jj = tid & 31;    // which float4 within that timestep (B:0-15, C:16-31)

    float4 rBC, rS;
    rS = make_float4(0.f, 0.f, 0.f, 0.f);
    {   // prologue: stage batch 0 into registers
        int t = tt;
        const float* src = (jj < 16)
            ? (g_Bm + (size_t)(t*64 + b)*64 + jj*4)
            : (g_Cm + (size_t)(t*64 + b)*64 + (jj - 16)*4);
        rBC = *(const float4*)src;
        if (tid < 128) {
            int t2 = tid >> 4, hh = tid & 15;
            rS = g_sdu[(size_t)(t2*64 + b)*16 + hh];
        }
    }

    int buf = 0;
    for (int t0 = 0; t0 < T_; t0 += 8) {
        // commit staged registers to smem[buf]
        if (jj < 16) *(float4*)&sB[buf][tt][jj*4]        = rBC;
        else         *(float4*)&sC[buf][tt][(jj - 16)*4] = rBC;
        if (tid < 128) sS[buf][tid >> 4][tid & 15] = rS;
        __syncthreads();

        // issue next batch's global loads (in flight during compute)
        int tn = t0 + 8;
        if (tn < T_) {
            int t = tn + tt;
            const float* src = (jj < 16)
                ? (g_Bm + (size_t)(t*64 + b)*64 + jj*4)
                : (g_Cm + (size_t)(t*64 + b)*64 + (jj - 16)*4);
            rBC = *(const float4*)src;
            if (tid < 128) {
                int t2 = tn + (tid >> 4), hh = tid & 15;
                rS = g_sdu[(size_t)(t2*64 + b)*16 + hh];
            }
        }

        // sequential recurrence over the 8 staged timesteps
        #pragma unroll
        for (int q = 0; q < 8; q++) {
            float B1 = sB[buf][q][lane];
            float B2 = sB[buf][q][lane + 32];
            float C1 = sC[buf][q][lane];
            float C2 = sC[buf][q][lane + 32];
            float4 s = sS[buf][q][h];
            g1 = fmaf(g1, s.y, s.x * B1);
            g2 = fmaf(g2, s.y, s.x * B2);
            float y = fmaf(g1, C1, g2 * C2);
            y += __shfl_xor_sync(0xffffffffu, y, 16);
            y += __shfl_xor_sync(0xffffffffu, y, 8);
            y += __shfl_xor_sync(0xffffffffu, y, 4);
            y += __shfl_xor_sync(0xffffffffu, y, 2);
            y += __shfl_xor_sync(0xffffffffu, y, 1);
            if (lane == 0)
                g_part[(size_t)((t0 + q)*64 + b)*16 + h] = y + s.z;
        }
        buf ^= 1;
    }
}

// ---------------------------------------------------------------------------
// reduce: out[t,b] = sum_h part[t,b,h]; replicate to fill out_size
// (reference returns (q, logits) with logits == q)
// ---------------------------------------------------------------------------
__global__ void reduce_kernel(float* __restrict__ out, int out_size) {
    int idx = blockIdx.x * blockDim.x + threadIdx.x;
    if (idx >= TB) return;
    const float4* p = (const float4*)(g_part + (size_t)idx*16);
    float4 a = p[0], b = p[1], c = p[2], d = p[3];
    float v = ((a.x + a.y) + (a.z + a.w)) + ((b.x + b.y) + (b.z + b.w))
            + ((c.x + c.y) + (c.z + c.w)) + ((d.x + d.y) + (d.z + d.w));
    for (int j = idx; j < out_size; j += TB) out[j] = v;
}

// ---------------------------------------------------------------------------
extern "C" void kernel_launch(void* const* d_in, const int* in_sizes, int n_in,
                              void* d_out, int out_size) {
    const float* obs     = (const float*)d_in[0];
    const float* reward  = (const float*)d_in[1];
    const float* W_in    = (const float*)d_in[2];
    const float* W_B     = (const float*)d_in[3];
    const float* W_C     = (const float*)d_in[4];
    const float* W_dt    = (const float*)d_in[5];
    const float* dt_b    = (const float*)d_in[6];
    const float* A_log   = (const float*)d_in[7];
    const float* Dv      = (const float*)d_in[8];
    const float* W_out   = (const float*)d_in[9];
    const float* init    = (const float*)d_in[10];
    float* out = (float*)d_out;

    cudaFuncSetAttribute(proj_kernel,
                         cudaFuncAttributeMaxDynamicSharedMemorySize, PROJ_SMEM);

    prep_kernel<<<8, 256>>>(W_in, W_out, init);
    proj_kernel<<<TB/64, 256, PROJ_SMEM>>>(obs, reward, W_B, W_C,
                                           W_dt, dt_b, A_log, Dv);
    scan_kernel<<<BK*2, 256>>>();
    reduce_kernel<<<(TB + 255)/256, 256>>>(out, out_size);
}

// round 2
// speedup vs baseline: 1.3739x; 1.3739x over previous
#include <cuda_runtime.h>
#include <math.h>

#define T_   2048
#define BK   64
#define H_   16
#define N_   64
#define OBS_ 64
#define TB   (T_*BK)        // 131072 rows
#define NC   8              // chunks
#define CH   (T_/NC)        // 256 steps per chunk
#define PROJ_SMEM ((64*65 + 64*64 + 64*64 + 64*16)*4)   // 53504 bytes

// -------- device scratch (static; no allocations anywhere) --------
__device__ float2 g_BC [(size_t)TB*N_];       // 67 MB  (B,C) interleaved per (t,b,n)
__device__ float4 g_sdu[(size_t)TB*H_];       // 33.5 MB (s, dec, du, 0) per (t,b,h)
__device__ float2 g_yD [(size_t)TB*H_];       // 16.8 MB (y_local+du, D_t)
__device__ float  g_end [NC*BK*H_*N_];        // 2 MB  chunk-local final states
__device__ float  g_init[NC*BK*H_*N_];        // 2 MB  chunk initial states
__device__ float  g_V[OBS_*H_];               // W_in folded with W_out (64x16)
__device__ float  g_g0[H_*N_];                // init_state folded with W_out

// ---------------------------------------------------------------------------
// prep: V[o,h] = sum_p W_in[o, h*64+p] * W_out[h*64+p]
//       g0[h,n] = sum_p init[h,p,n] * W_out[h*64+p]
// ---------------------------------------------------------------------------
__global__ void prep_kernel(const float* __restrict__ W_in,
                            const float* __restrict__ W_out,
                            const float* __restrict__ init_state) {
    int tid = blockIdx.x * blockDim.x + threadIdx.x;
    if (tid < OBS_ * H_) {
        int o = tid >> 4, h = tid & 15;
        float acc = 0.f;
        #pragma unroll 8
        for (int p = 0; p < 64; p++)
            acc = fmaf(W_in[o*1024 + h*64 + p], W_out[h*64 + p], acc);
        g_V[o*H_ + h] = acc;
    } else if (tid < OBS_*H_ + H_*N_) {
        int i = tid - OBS_*H_;
        int h = i >> 6, n = i & 63;
        float acc = 0.f;
        #pragma unroll 8
        for (int p = 0; p < 64; p++)
            acc = fmaf(init_state[(h*64 + p)*64 + n], W_out[h*64 + p], acc);
        g_g0[i] = acc;
    }
}

// ---------------------------------------------------------------------------
// proj: GEMM obs(131072x64) @ [W_B | W_C | V](64x144) + softplus/exp epilogue.
// Block = 64 rows. Thread (ty,tx) of 16x16: rows ty+16i, B/C cols tx*4..tx*4+3,
// dt col h=tx. Writes interleaved (B,C) float2 via STG.128.
// ---------------------------------------------------------------------------
__global__ void proj_kernel(const float* __restrict__ obs,
                            const float* __restrict__ reward,
                            const float* __restrict__ W_B,
                            const float* __restrict__ W_C,
                            const float* __restrict__ W_dt,
                            const float* __restrict__ dt_bias,
                            const float* __restrict__ A_log,
                            const float* __restrict__ Dv) {
    extern __shared__ float sm[];
    float* sO  = sm;                 // [64][65]
    float* sWB = sO  + 64*65;        // [64][64]
    float* sWC = sWB + 64*64;        // [64][64]
    float* sV  = sWC + 64*64;        // [64][16]

    int tid = threadIdx.x;
    for (int i = tid; i < 1024; i += 256) {
        ((float4*)sWB)[i] = ((const float4*)W_B)[i];
        ((float4*)sWC)[i] = ((const float4*)W_C)[i];
    }
    ((float4*)sV)[tid] = ((const float4*)g_V)[tid];

    int row0 = blockIdx.x * 64;
    for (int i = tid; i < 1024; i += 256) {          // 64 rows * 16 float4
        int r = i >> 4, c4 = i & 15;
        float4 v = *(const float4*)(obs + (size_t)(row0 + r)*64 + c4*4);
        float* d = sO + r*65 + c4*4;
        d[0] = v.x; d[1] = v.y; d[2] = v.z; d[3] = v.w;
    }
    __syncthreads();

    int ty = tid >> 4, tx = tid & 15;
    float aB[4][4], aC[4][4], aS[4];
    #pragma unroll
    for (int i = 0; i < 4; i++) {
        aS[i] = 0.f;
        #pragma unroll
        for (int q = 0; q < 4; q++) { aB[i][q] = 0.f; aC[i][q] = 0.f; }
    }

    #pragma unroll 4
    for (int k = 0; k < 64; k++) {
        float4 wb = *(const float4*)(sWB + k*64 + tx*4);
        float4 wc = *(const float4*)(sWC + k*64 + tx*4);
        float  wv = sV[k*16 + tx];
        float a0 = sO[(ty     )*65 + k];
        float a1 = sO[(ty + 16)*65 + k];
        float a2 = sO[(ty + 32)*65 + k];
        float a3 = sO[(ty + 48)*65 + k];
        float a[4] = {a0, a1, a2, a3};
        #pragma unroll
        for (int i = 0; i < 4; i++) {
            aB[i][0] = fmaf(a[i], wb.x, aB[i][0]);
            aB[i][1] = fmaf(a[i], wb.y, aB[i][1]);
            aB[i][2] = fmaf(a[i], wb.z, aB[i][2]);
            aB[i][3] = fmaf(a[i], wb.w, aB[i][3]);
            aC[i][0] = fmaf(a[i], wc.x, aC[i][0]);
            aC[i][1] = fmaf(a[i], wc.y, aC[i][1]);
            aC[i][2] = fmaf(a[i], wc.z, aC[i][2]);
            aC[i][3] = fmaf(a[i], wc.w, aC[i][3]);
            aS[i]    = fmaf(a[i], wv,   aS[i]);
        }
    }

    float wdt = W_dt[tx], bdt = dt_bias[tx];
    float A   = -expf(A_log[tx]);
    float dh  = Dv[tx];

    #pragma unroll
    for (int i = 0; i < 4; i++) {
        int row = row0 + ty + 16*i;
        float2* dst = g_BC + (size_t)row*64 + tx*4;
        float4 p0 = make_float4(aB[i][0], aC[i][0], aB[i][1], aC[i][1]);
        float4 p1 = make_float4(aB[i][2], aC[i][2], aB[i][3], aC[i][3]);
        *(float4*)(dst)     = p0;
        *(float4*)(dst + 2) = p1;

        float x   = fmaf(reward[row], wdt, bdt);
        float dtv = fmaxf(x, 0.f) + log1pf(expf(-fabsf(x)));   // softplus
        float dec = expf(dtv * A);
        g_sdu[(size_t)row*16 + tx] = make_float4(dtv * aS[i], dec, dh * aS[i], 0.f);
    }
}

// ---------------------------------------------------------------------------
// scan1: chunk-local scans. 8192 warp-chains = (b, h, chunk). Each warp owns
// states n = {lane, lane+32}, starts from g=0, records y_local+du and the
// running decay product D_t per timestep, plus chunk-final states.
// ---------------------------------------------------------------------------
__global__ void scan1_kernel() {
    int chain = blockIdx.x * 8 + (threadIdx.x >> 5);
    int lane  = threadIdx.x & 31;
    int c = chain & 7;
    int h = (chain >> 3) & 15;
    int b = chain >> 7;

    float g1 = 0.f, g2 = 0.f, D = 1.f;
    int t0 = c * CH;

    #pragma unroll 4
    for (int q = 0; q < CH; q++) {
        size_t row = (size_t)(t0 + q)*64 + b;
        float2 bc1 = g_BC[row*64 + lane];
        float2 bc2 = g_BC[row*64 + lane + 32];
        float4 s   = g_sdu[row*16 + h];
        g1 = fmaf(g1, s.y, s.x * bc1.x);
        g2 = fmaf(g2, s.y, s.x * bc2.x);
        D *= s.y;
        float y = fmaf(g1, bc1.y, g2 * bc2.y);
        y += __shfl_xor_sync(0xffffffffu, y, 16);
        y += __shfl_xor_sync(0xffffffffu, y, 8);
        y += __shfl_xor_sync(0xffffffffu, y, 4);
        y += __shfl_xor_sync(0xffffffffu, y, 2);
        y += __shfl_xor_sync(0xffffffffu, y, 1);
        if (lane == 0)
            g_yD[row*16 + h] = make_float2(y + s.z, D);
    }
    int e = ((c*64 + b)*16 + h)*64;
    g_end[e + lane]      = g1;
    g_end[e + lane + 32] = g2;
}

// ---------------------------------------------------------------------------
// scan2: stitch chunk initial states: G_0 = g0; G_c = g_end_{c-1} + P_{c-1} G_{c-1}
// 1024 warps, one per (b,h); 8 sequential chunk steps.
// ---------------------------------------------------------------------------
__global__ void scan2_kernel() {
    int chain = blockIdx.x * 8 + (threadIdx.x >> 5);
    int lane  = threadIdx.x & 31;
    int h = chain & 15, b = chain >> 4;

    float g1 = g_g0[h*64 + lane];
    float g2 = g_g0[h*64 + lane + 32];
    int gi0 = ((0*64 + b)*16 + h)*64;
    g_init[gi0 + lane]      = g1;
    g_init[gi0 + lane + 32] = g2;

    for (int c = 1; c < NC; c++) {
        float P = g_yD[((size_t)(c*CH - 1)*64 + b)*16 + h].y;
        int e = (((c-1)*64 + b)*16 + h)*64;
        g1 = fmaf(g1, P, g_end[e + lane]);
        g2 = fmaf(g2, P, g_end[e + lane + 32]);
        int gi = ((c*64 + b)*16 + h)*64;
        g_init[gi + lane]      = g1;
        g_init[gi + lane + 32] = g2;
    }
}

// ---------------------------------------------------------------------------
// scan3: correction + head-sum + output. Block per (b,chunk), 8 warps; warp w
// owns 32 timesteps. Chunk initial states for all 16 heads live in registers.
// out[t*64+b] = sum_h [ y_local + D_t * sum_n G_c[h,n] C_t[n] ]
// ---------------------------------------------------------------------------
__global__ void scan3_kernel(float* __restrict__ out, int out_size) {
    int b = blockIdx.x >> 3, c = blockIdx.x & 7;
    int lane = threadIdx.x & 31;
    int w    = threadIdx.x >> 5;

    float gi1[16], gi2[16];
    #pragma unroll
    for (int h = 0; h < 16; h++) {
        int gi = ((c*64 + b)*16 + h)*64;
        gi1[h] = g_init[gi + lane];
        gi2[h] = g_init[gi + lane + 32];
    }

    int tbase = c*CH + w*32;
    for (int q = 0; q < 32; q++) {
        size_t row = (size_t)(tbase + q)*64 + b;
        float2 bc1 = g_BC[row*64 + lane];
        float2 bc2 = g_BC[row*64 + lane + 32];
        float2 yD  = make_float2(0.f, 0.f);
        if (lane < 16) yD = g_yD[row*16 + lane];
        float acc = yD.x;
        #pragma unroll
        for (int h = 0; h < 16; h++) {
            float Dh = __shfl_sync(0xffffffffu, yD.y, h);
            float tl = fmaf(gi2[h], bc2.y, gi1[h]*bc1.y);
            acc = fmaf(Dh, tl, acc);
        }
        acc += __shfl_xor_sync(0xffffffffu, acc, 16);
        acc += __shfl_xor_sync(0xffffffffu, acc, 8);
        acc += __shfl_xor_sync(0xffffffffu, acc, 4);
        acc += __shfl_xor_sync(0xffffffffu, acc, 2);
        acc += __shfl_xor_sync(0xffffffffu, acc, 1);
        if (lane == 0) {
            int idx = (tbase + q)*64 + b;
            for (int j = idx; j < out_size; j += TB) out[j] = acc;
        }
    }
}

// ---------------------------------------------------------------------------
extern "C" void kernel_launch(void* const* d_in, const int* in_sizes, int n_in,
                              void* d_out, int out_size) {
    const float* obs     = (const float*)d_in[0];
    const float* reward  = (const float*)d_in[1];
    const float* W_in    = (const float*)d_in[2];
    const float* W_B     = (const float*)d_in[3];
    const float* W_C     = (const float*)d_in[4];
    const float* W_dt    = (const float*)d_in[5];
    const float* dt_b    = (const float*)d_in[6];
    const float* A_log   = (const float*)d_in[7];
    const float* Dv      = (const float*)d_in[8];
    const float* W_out   = (const float*)d_in[9];
    const float* init    = (const float*)d_in[10];
    float* out = (float*)d_out;

    cudaFuncSetAttribute(proj_kernel,
                         cudaFuncAttributeMaxDynamicSharedMemorySize, PROJ_SMEM);

    prep_kernel<<<8, 256>>>(W_in, W_out, init);
    proj_kernel<<<TB/64, 256, PROJ_SMEM>>>(obs, reward, W_B, W_C,
                                           W_dt, dt_b, A_log, Dv);
    scan1_kernel<<<BK*H_*NC/8, 256>>>();
    scan2_kernel<<<BK*H_/8, 256>>>();
    scan3_kernel<<<BK*NC, 256>>>(out, out_size);
}

// round 3
// speedup vs baseline: 1.7448x; 1.2700x over previous
#include <cuda_runtime.h>
#include <math.h>

#define T_   2048
#define BK   64
#define H_   16
#define N_   64
#define OBS_ 64
#define TB   (T_*BK)        // 131072 rows
#define NC   8              // chunks
#define CH   (T_/NC)        // 256 steps per chunk
#define PROJ_SMEM ((64*65 + 64*64 + 64*64 + 64*16)*4)   // 53504 bytes

// -------- device scratch (static; no allocations anywhere) --------
__device__ float2 g_BC [(size_t)TB*N_];       // 67 MB  (B,C) interleaved per (t,b,n)
__device__ float4 g_sdu[(size_t)TB*H_];       // 33.5 MB (s, dec, du, 0) per (t,b,h)
__device__ float2 g_yD [(size_t)TB*H_];       // 16.8 MB (y_local+du, D_t)
__device__ float  g_end [NC*BK*H_*N_];        // 2 MB  chunk-local final states
__device__ float  g_init[NC*BK*H_*N_];        // 2 MB  chunk initial states
__device__ float  g_V[OBS_*H_];               // W_in folded with W_out (64x16)
__device__ float  g_g0[H_*N_];                // init_state folded with W_out

// ---- packed f32x2 helpers (sm_103a FFMA2 path) ----
__device__ __forceinline__ unsigned long long pack2(float x) {
    unsigned long long r;
    asm("mov.b64 %0, {%1, %1};" : "=l"(r) : "f"(x));
    return r;
}
__device__ __forceinline__ void fma2(unsigned long long& d,
                                     unsigned long long a,
                                     unsigned long long b) {
    asm("fma.rn.f32x2 %0, %1, %2, %0;" : "+l"(d) : "l"(a), "l"(b));
}
__device__ __forceinline__ float2 unpack2(unsigned long long v) {
    float lo, hi;
    asm("mov.b64 {%0, %1}, %2;" : "=f"(lo), "=f"(hi) : "l"(v));
    return make_float2(lo, hi);
}

// ---------------------------------------------------------------------------
// prep: V[o,h] = sum_p W_in[o, h*64+p] * W_out[h*64+p]
//       g0[h,n] = sum_p init[h,p,n] * W_out[h*64+p]
// ---------------------------------------------------------------------------
__global__ void prep_kernel(const float* __restrict__ W_in,
                            const float* __restrict__ W_out,
                            const float* __restrict__ init_state) {
    int tid = blockIdx.x * blockDim.x + threadIdx.x;
    if (tid < OBS_ * H_) {
        int o = tid >> 4, h = tid & 15;
        float acc = 0.f;
        #pragma unroll 8
        for (int p = 0; p < 64; p++)
            acc = fmaf(W_in[o*1024 + h*64 + p], W_out[h*64 + p], acc);
        g_V[o*H_ + h] = acc;
    } else if (tid < OBS_*H_ + H_*N_) {
        int i = tid - OBS_*H_;
        int h = i >> 6, n = i & 63;
        float acc = 0.f;
        #pragma unroll 8
        for (int p = 0; p < 64; p++)
            acc = fmaf(init_state[(h*64 + p)*64 + n], W_out[h*64 + p], acc);
        g_g0[i] = acc;
    }
}

// ---------------------------------------------------------------------------
// proj: GEMM obs(131072x64) @ [W_B | W_C | V](64x144) via packed f32x2 FMA.
// Block = 64 rows, 256 threads (16x16). Thread: 4 rows, B cols tx*4..+3,
// C cols tx*4..+3, dt col h=tx. Outputs interleaved (B,C) + sdu epilogue.
// ---------------------------------------------------------------------------
__global__ void proj_kernel(const float* __restrict__ obs,
                            const float* __restrict__ reward,
                            const float* __restrict__ W_B,
                            const float* __restrict__ W_C,
                            const float* __restrict__ W_dt,
                            const float* __restrict__ dt_bias,
                            const float* __restrict__ A_log,
                            const float* __restrict__ Dv) {
    extern __shared__ float sm[];
    float* sO  = sm;                 // [64][65]
    float* sWB = sO  + 64*65;        // [64][64]
    float* sWC = sWB + 64*64;        // [64][64]
    float* sV  = sWC + 64*64;        // [64][16]

    int tid = threadIdx.x;
    for (int i = tid; i < 1024; i += 256) {
        ((float4*)sWB)[i] = ((const float4*)W_B)[i];
        ((float4*)sWC)[i] = ((const float4*)W_C)[i];
    }
    ((float4*)sV)[tid] = ((const float4*)g_V)[tid];

    int row0 = blockIdx.x * 64;
    for (int i = tid; i < 1024; i += 256) {          // 64 rows * 16 float4
        int r = i >> 4, c4 = i & 15;
        float4 v = *(const float4*)(obs + (size_t)(row0 + r)*64 + c4*4);
        float* d = sO + r*65 + c4*4;
        d[0] = v.x; d[1] = v.y; d[2] = v.z; d[3] = v.w;
    }
    __syncthreads();

    int ty = tid >> 4, tx = tid & 15;
    unsigned long long aB0[4], aB1[4], aC0[4], aC1[4];
    float aS[4];
    #pragma unroll
    for (int i = 0; i < 4; i++) {
        aB0[i] = 0ull; aB1[i] = 0ull; aC0[i] = 0ull; aC1[i] = 0ull;
        aS[i] = 0.f;
    }

    #pragma unroll 4
    for (int k = 0; k < 64; k++) {
        const unsigned long long* pwb =
            (const unsigned long long*)(sWB + k*64 + tx*4);
        const unsigned long long* pwc =
            (const unsigned long long*)(sWC + k*64 + tx*4);
        unsigned long long wb01 = pwb[0], wb23 = pwb[1];
        unsigned long long wc01 = pwc[0], wc23 = pwc[1];
        float wv = sV[k*16 + tx];
        float a0 = sO[(ty     )*65 + k];
        float a1 = sO[(ty + 16)*65 + k];
        float a2 = sO[(ty + 32)*65 + k];
        float a3 = sO[(ty + 48)*65 + k];
        float a[4] = {a0, a1, a2, a3};
        #pragma unroll
        for (int i = 0; i < 4; i++) {
            unsigned long long aa = pack2(a[i]);
            fma2(aB0[i], aa, wb01);
            fma2(aB1[i], aa, wb23);
            fma2(aC0[i], aa, wc01);
            fma2(aC1[i], aa, wc23);
            aS[i] = fmaf(a[i], wv, aS[i]);
        }
    }

    float wdt = W_dt[tx], bdt = dt_bias[tx];
    float A   = -expf(A_log[tx]);
    float dh  = Dv[tx];

    #pragma unroll
    for (int i = 0; i < 4; i++) {
        int row = row0 + ty + 16*i;
        float2 b01 = unpack2(aB0[i]);
        float2 b23 = unpack2(aB1[i]);
        float2 c01 = unpack2(aC0[i]);
        float2 c23 = unpack2(aC1[i]);
        float2* dst = g_BC + (size_t)row*64 + tx*4;
        *(float4*)(dst)     = make_float4(b01.x, c01.x, b01.y, c01.y);
        *(float4*)(dst + 2) = make_float4(b23.x, c23.x, b23.y, c23.y);

        float x   = fmaf(reward[row], wdt, bdt);
        float dtv = fmaxf(x, 0.f) + log1pf(expf(-fabsf(x)));   // softplus
        float dec = expf(dtv * A);
        g_sdu[(size_t)row*16 + tx] = make_float4(dtv * aS[i], dec, dh * aS[i], 0.f);
    }
}

// ---------------------------------------------------------------------------
// scan1: chunk-local scans. CTA = (b, chunk), 256 threads = 8 warps.
// Each warp handles 2 heads (16 lanes/head, 4 states/lane). B/C + sdu are
// staged in double-buffered smem (read from global ONCE per CTA, shared by
// all 16 heads — kills the 16x redundant L2 traffic of round 2).
// ---------------------------------------------------------------------------
__global__ void scan1_kernel() {
    __shared__ float2 sBC[2][8][64];   // 8 KB
    __shared__ float4 sS [2][8][16];   // 4 KB

    int b = blockIdx.x >> 3, c = blockIdx.x & 7;
    int tid  = threadIdx.x;
    int w    = tid >> 5;
    int lane = tid & 31;
    int half = lane >> 4;          // which head of the pair
    int li   = lane & 15;          // owns states n = 4*li .. 4*li+3
    int h    = 2*w + half;

    float g0 = 0.f, g1 = 0.f, g2 = 0.f, g3 = 0.f, D = 1.f;
    int t0 = c * CH;

    // staging roles: tid<256 all load BC (256 float4), tid<128 also load sdu
    int qr = tid >> 5, jr = tid & 31;          // BC: row qr, float4 jr
    int q2 = (tid & 127) >> 4, h2 = tid & 15;  // sdu: row q2, head h2
    bool ldS = tid < 128;

    float4 rBC, rS = make_float4(0.f,0.f,0.f,0.f);
    {   // prologue: stage batch 0
        rBC = ((const float4*)(g_BC + ((size_t)((t0 + qr)*64 + b))*64))[jr];
        if (ldS) rS = g_sdu[((size_t)((t0 + q2)*64 + b))*16 + h2];
    }

    int buf = 0;
    for (int tb = t0; tb < t0 + CH; tb += 8) {
        *(float4*)&sBC[buf][qr][jr*2] = rBC;
        if (ldS) sS[buf][q2][h2] = rS;
        __syncthreads();

        int tn = tb + 8;
        if (tn < t0 + CH) {
            rBC = ((const float4*)(g_BC + ((size_t)((tn + qr)*64 + b))*64))[jr];
            if (ldS) rS = g_sdu[((size_t)((tn + q2)*64 + b))*16 + h2];
        }

        #pragma unroll
        for (int q = 0; q < 8; q++) {
            float4 bcA = *(const float4*)&sBC[buf][q][4*li];     // n=4li,4li+1
            float4 bcB = *(const float4*)&sBC[buf][q][4*li + 2]; // n=4li+2,+3
            float4 s   = sS[buf][q][h];
            float sx = s.x;
            g0 = fmaf(g0, s.y, sx*bcA.x);
            g1 = fmaf(g1, s.y, sx*bcA.z);
            g2 = fmaf(g2, s.y, sx*bcB.x);
            g3 = fmaf(g3, s.y, sx*bcB.z);
            D *= s.y;
            float y = fmaf(g0, bcA.y,
                      fmaf(g1, bcA.w,
                      fmaf(g2, bcB.y, g3*bcB.w)));
            y += __shfl_xor_sync(0xffffffffu, y, 8);
            y += __shfl_xor_sync(0xffffffffu, y, 4);
            y += __shfl_xor_sync(0xffffffffu, y, 2);
            y += __shfl_xor_sync(0xffffffffu, y, 1);
            if (li == 0)
                g_yD[((size_t)(tb + q)*64 + b)*16 + h] = make_float2(y + s.z, D);
        }
        buf ^= 1;
    }
    int e = ((c*64 + b)*16 + h)*64;
    *(float4*)&g_end[e + 4*li] = make_float4(g0, g1, g2, g3);
}

// ---------------------------------------------------------------------------
// scan2: stitch chunk initial states. One warp per (b,h). All loads issued
// upfront (independent), then an 8-step FMA chain.
// ---------------------------------------------------------------------------
__global__ void scan2_kernel() {
    int chain = blockIdx.x * 8 + (threadIdx.x >> 5);
    int lane  = threadIdx.x & 31;
    int h = chain & 15, b = chain >> 4;

    float P[NC-1], e1[NC-1], e2[NC-1];
    #pragma unroll
    for (int c = 0; c < NC-1; c++) {
        P[c] = g_yD[((size_t)((c+1)*CH - 1)*64 + b)*16 + h].y;
        int e = ((c*64 + b)*16 + h)*64;
        e1[c] = g_end[e + lane];
        e2[c] = g_end[e + lane + 32];
    }
    float g1 = g_g0[h*64 + lane];
    float g2 = g_g0[h*64 + lane + 32];
    int gi = ((0*64 + b)*16 + h)*64;
    g_init[gi + lane]      = g1;
    g_init[gi + lane + 32] = g2;
    #pragma unroll
    for (int c = 1; c < NC; c++) {
        g1 = fmaf(g1, P[c-1], e1[c-1]);
        g2 = fmaf(g2, P[c-1], e2[c-1]);
        gi = ((c*64 + b)*16 + h)*64;
        g_init[gi + lane]      = g1;
        g_init[gi + lane + 32] = g2;
    }
}

// ---------------------------------------------------------------------------
// scan3: correction + head-sum + output. Block per (b,chunk), 8 warps; warp w
// owns 32 timesteps. Chunk initial states for all 16 heads live in registers.
// out[t*64+b] = sum_h [ y_local + D_t * sum_n G_c[h,n] C_t[n] ]
// ---------------------------------------------------------------------------
__global__ void scan3_kernel(float* __restrict__ out, int out_size) {
    int b = blockIdx.x >> 3, c = blockIdx.x & 7;
    int lane = threadIdx.x & 31;
    int w    = threadIdx.x >> 5;

    float gi1[16], gi2[16];
    #pragma unroll
    for (int h = 0; h < 16; h++) {
        int gi = ((c*64 + b)*16 + h)*64;
        gi1[h] = g_init[gi + lane];
        gi2[h] = g_init[gi + lane + 32];
    }

    int tbase = c*CH + w*32;
    for (int q = 0; q < 32; q++) {
        size_t row = (size_t)(tbase + q)*64 + b;
        float2 bc1 = g_BC[row*64 + lane];
        float2 bc2 = g_BC[row*64 + lane + 32];
        float2 yD  = make_float2(0.f, 0.f);
        if (lane < 16) yD = g_yD[row*16 + lane];
        float acc = yD.x;
        #pragma unroll
        for (int h = 0; h < 16; h++) {
            float Dh = __shfl_sync(0xffffffffu, yD.y, h);
            float tl = fmaf(gi2[h], bc2.y, gi1[h]*bc1.y);
            acc = fmaf(Dh, tl, acc);
        }
        acc += __shfl_xor_sync(0xffffffffu, acc, 16);
        acc += __shfl_xor_sync(0xffffffffu, acc, 8);
        acc += __shfl_xor_sync(0xffffffffu, acc, 4);
        acc += __shfl_xor_sync(0xffffffffu, acc, 2);
        acc += __shfl_xor_sync(0xffffffffu, acc, 1);
        if (lane == 0) {
            int idx = (tbase + q)*64 + b;
            for (int j = idx; j < out_size; j += TB) out[j] = acc;
        }
    }
}

// ---------------------------------------------------------------------------
extern "C" void kernel_launch(void* const* d_in, const int* in_sizes, int n_in,
                              void* d_out, int out_size) {
    const float* obs     = (const float*)d_in[0];
    const float* reward  = (const float*)d_in[1];
    const float* W_in    = (const float*)d_in[2];
    const float* W_B     = (const float*)d_in[3];
    const float* W_C     = (const float*)d_in[4];
    const float* W_dt    = (const float*)d_in[5];
    const float* dt_b    = (const float*)d_in[6];
    const float* A_log   = (const float*)d_in[7];
    const float* Dv      = (const float*)d_in[8];
    const float* W_out   = (const float*)d_in[9];
    const float* init    = (const float*)d_in[10];
    float* out = (float*)d_out;

    cudaFuncSetAttribute(proj_kernel,
                         cudaFuncAttributeMaxDynamicSharedMemorySize, PROJ_SMEM);

    prep_kernel<<<8, 256>>>(W_in, W_out, init);
    proj_kernel<<<TB/64, 256, PROJ_SMEM>>>(obs, reward, W_B, W_C,
                                           W_dt, dt_b, A_log, Dv);
    scan1_kernel<<<BK*NC, 256>>>();
    scan2_kernel<<<BK*H_/8, 256>>>();
    scan3_kernel<<<BK*NC, 256>>>(out, out_size);
}

// round 4
// speedup vs baseline: 2.1550x; 1.2351x over previous
#include <cuda_runtime.h>
#include <math.h>

#define T_   2048
#define BK   64
#define H_   16
#define N_   64
#define OBS_ 64
#define TB   (T_*BK)        // 131072 rows
#define NC   16             // chunks
#define CH   (T_/NC)        // 128 steps per chunk
#define PROJ_SMEM ((64*65 + 64*64 + 64*64 + 64*16)*4)   // 53504 bytes

// -------- device scratch (static; all b-major: [b][t][...]) --------
__device__ float  g_B  [(size_t)TB*N_];       // 33.5 MB  B[b][t][n]
__device__ float  g_C  [(size_t)TB*N_];       // 33.5 MB  C[b][t][n]
__device__ float2 g_sd [(size_t)TB*H_];       // 16.8 MB  (s, dec)[b][t][h]
__device__ float  g_du [(size_t)TB*H_];       // 8.4 MB   du[b][t][h]
__device__ float2 g_yD [(size_t)TB*H_];       // 16.8 MB  (y_local+du, D)[b][t][h]
__device__ float  g_end [NC*BK*H_*N_];        // 4 MB  chunk-local final states
__device__ float  g_init[NC*BK*H_*N_];        // 4 MB  chunk initial states
__device__ float  g_V[OBS_*H_];               // W_in folded with W_out (64x16)
__device__ float  g_g0[H_*N_];                // init_state folded with W_out

// ---- packed f32x2 helpers (sm_103a FFMA2 path) ----
__device__ __forceinline__ unsigned long long pack2(float x) {
    unsigned long long r;
    asm("mov.b64 %0, {%1, %1};" : "=l"(r) : "f"(x));
    return r;
}
__device__ __forceinline__ void fma2(unsigned long long& d,
                                     unsigned long long a,
                                     unsigned long long b) {
    asm("fma.rn.f32x2 %0, %1, %2, %0;" : "+l"(d) : "l"(a), "l"(b));
}
__device__ __forceinline__ float2 unpack2(unsigned long long v) {
    float lo, hi;
    asm("mov.b64 {%0, %1}, %2;" : "=f"(lo), "=f"(hi) : "l"(v));
    return make_float2(lo, hi);
}

// ---------------------------------------------------------------------------
// prep: V[o,h] = sum_p W_in[o, h*64+p] * W_out[h*64+p]
//       g0[h,n] = sum_p init[h,p,n] * W_out[h*64+p]
// ---------------------------------------------------------------------------
__global__ void prep_kernel(const float* __restrict__ W_in,
                            const float* __restrict__ W_out,
                            const float* __restrict__ init_state) {
    int tid = blockIdx.x * blockDim.x + threadIdx.x;
    if (tid < OBS_ * H_) {
        int o = tid >> 4, h = tid & 15;
        float acc = 0.f;
        #pragma unroll 8
        for (int p = 0; p < 64; p++)
            acc = fmaf(W_in[o*1024 + h*64 + p], W_out[h*64 + p], acc);
        g_V[o*H_ + h] = acc;
    } else if (tid < OBS_*H_ + H_*N_) {
        int i = tid - OBS_*H_;
        int h = i >> 6, n = i & 63;
        float acc = 0.f;
        #pragma unroll 8
        for (int p = 0; p < 64; p++)
            acc = fmaf(init_state[(h*64 + p)*64 + n], W_out[h*64 + p], acc);
        g_g0[i] = acc;
    }
}

// ---------------------------------------------------------------------------
// proj: GEMM obs(131072x64) @ [W_B | W_C | V](64x144) via packed f32x2 FMA.
// Block = 64 consecutive t-major rows = one t, all 64 b. Outputs stored
// b-major so the scan kernels stream contiguously.
// ---------------------------------------------------------------------------
__global__ void proj_kernel(const float* __restrict__ obs,
                            const float* __restrict__ reward,
                            const float* __restrict__ W_B,
                            const float* __restrict__ W_C,
                            const float* __restrict__ W_dt,
                            const float* __restrict__ dt_bias,
                            const float* __restrict__ A_log,
                            const float* __restrict__ Dv) {
    extern __shared__ float sm[];
    float* sO  = sm;                 // [64][65]
    float* sWB = sO  + 64*65;        // [64][64]
    float* sWC = sWB + 64*64;        // [64][64]
    float* sV  = sWC + 64*64;        // [64][16]

    int tid = threadIdx.x;
    for (int i = tid; i < 1024; i += 256) {
        ((float4*)sWB)[i] = ((const float4*)W_B)[i];
        ((float4*)sWC)[i] = ((const float4*)W_C)[i];
    }
    ((float4*)sV)[tid] = ((const float4*)g_V)[tid];

    int row0 = blockIdx.x * 64;
    int t    = row0 >> 6;            // all 64 rows share this t
    for (int i = tid; i < 1024; i += 256) {          // 64 rows * 16 float4
        int r = i >> 4, c4 = i & 15;
        float4 v = *(const float4*)(obs + (size_t)(row0 + r)*64 + c4*4);
        float* d = sO + r*65 + c4*4;
        d[0] = v.x; d[1] = v.y; d[2] = v.z; d[3] = v.w;
    }
    __syncthreads();

    int ty = tid >> 4, tx = tid & 15;
    unsigned long long aB0[4], aB1[4], aC0[4], aC1[4];
    float aS[4];
    #pragma unroll
    for (int i = 0; i < 4; i++) {
        aB0[i] = 0ull; aB1[i] = 0ull; aC0[i] = 0ull; aC1[i] = 0ull;
        aS[i] = 0.f;
    }

    #pragma unroll 4
    for (int k = 0; k < 64; k++) {
        const unsigned long long* pwb =
            (const unsigned long long*)(sWB + k*64 + tx*4);
        const unsigned long long* pwc =
            (const unsigned long long*)(sWC + k*64 + tx*4);
        unsigned long long wb01 = pwb[0], wb23 = pwb[1];
        unsigned long long wc01 = pwc[0], wc23 = pwc[1];
        float wv = sV[k*16 + tx];
        float a0 = sO[(ty     )*65 + k];
        float a1 = sO[(ty + 16)*65 + k];
        float a2 = sO[(ty + 32)*65 + k];
        float a3 = sO[(ty + 48)*65 + k];
        float a[4] = {a0, a1, a2, a3};
        #pragma unroll
        for (int i = 0; i < 4; i++) {
            unsigned long long aa = pack2(a[i]);
            fma2(aB0[i], aa, wb01);
            fma2(aB1[i], aa, wb23);
            fma2(aC0[i], aa, wc01);
            fma2(aC1[i], aa, wc23);
            aS[i] = fmaf(a[i], wv, aS[i]);
        }
    }

    float wdt = W_dt[tx], bdt = dt_bias[tx];
    float A   = -expf(A_log[tx]);
    float dh  = Dv[tx];

    #pragma unroll
    for (int i = 0; i < 4; i++) {
        int b   = ty + 16*i;
        int row = row0 + b;                          // t*64 + b (reward index)
        size_t base = (size_t)b*T_ + t;              // b-major row index
        float2 b01 = unpack2(aB0[i]);
        float2 b23 = unpack2(aB1[i]);
        float2 c01 = unpack2(aC0[i]);
        float2 c23 = unpack2(aC1[i]);
        *(float4*)(g_B + base*64 + tx*4) = make_float4(b01.x, b01.y, b23.x, b23.y);
        *(float4*)(g_C + base*64 + tx*4) = make_float4(c01.x, c01.y, c23.x, c23.y);

        float x   = fmaf(reward[row], wdt, bdt);
        float dtv = fmaxf(x, 0.f) + log1pf(expf(-fabsf(x)));   // softplus
        float dec = expf(dtv * A);
        g_sd[base*16 + tx] = make_float2(dtv * aS[i], dec);
        g_du[base*16 + tx] = dh * aS[i];
    }
}

// ---------------------------------------------------------------------------
// scan1: chunk-local scans. CTA = (b, chunk): streams CONTIGUOUS b-major data.
// 8 warps; each warp handles 2 heads (16 lanes/head, 4 states/lane). Inputs
// staged in double-buffered smem in 16-step batches (shared by all 16 heads).
// ---------------------------------------------------------------------------
__global__ void scan1_kernel() {
    __shared__ float  sB [2][16][64];   // 8 KB
    __shared__ float  sC [2][16][64];   // 8 KB
    __shared__ float2 sSD[2][16][16];   // 4 KB
    __shared__ float  sDU[2][16][16];   // 2 KB

    int b = blockIdx.x & 63, c = blockIdx.x >> 6;
    int tid  = threadIdx.x;
    int w    = tid >> 5;
    int lane = tid & 31;
    int half = lane >> 4;
    int li   = lane & 15;          // owns states n = 4*li .. 4*li+3
    int h    = 2*w + half;

    float g0 = 0.f, g1 = 0.f, g2 = 0.f, g3 = 0.f, D = 1.f;
    size_t bT = (size_t)b*T_;
    int t0 = c * CH;

    // staging roles (all 256 threads): B/C float4 (t = tid>>4, j = tid&15),
    // sd/du (t = tid>>4, h2 = tid&15)
    int st = tid >> 4, sj = tid & 15;

    float4 rB, rC; float2 rSD; float rDU;
    {   // prologue: stage batch 0
        size_t rbase = bT + t0 + st;
        rB  = ((const float4*)(g_B + rbase*64))[sj];
        rC  = ((const float4*)(g_C + rbase*64))[sj];
        rSD = g_sd[rbase*16 + sj];
        rDU = g_du[rbase*16 + sj];
    }

    int buf = 0;
    for (int tb = t0; tb < t0 + CH; tb += 16) {
        *(float4*)&sB[buf][st][sj*4] = rB;
        *(float4*)&sC[buf][st][sj*4] = rC;
        sSD[buf][st][sj] = rSD;
        sDU[buf][st][sj] = rDU;
        __syncthreads();

        int tn = tb + 16;
        if (tn < t0 + CH) {
            size_t rbase = bT + tn + st;
            rB  = ((const float4*)(g_B + rbase*64))[sj];
            rC  = ((const float4*)(g_C + rbase*64))[sj];
            rSD = g_sd[rbase*16 + sj];
            rDU = g_du[rbase*16 + sj];
        }

        #pragma unroll
        for (int q = 0; q < 16; q++) {
            float4 bv = *(const float4*)&sB[buf][q][4*li];
            float4 cv = *(const float4*)&sC[buf][q][4*li];
            float2 sd = sSD[buf][q][h];
            float  du = sDU[buf][q][h];
            g0 = fmaf(g0, sd.y, sd.x*bv.x);
            g1 = fmaf(g1, sd.y, sd.x*bv.y);
            g2 = fmaf(g2, sd.y, sd.x*bv.z);
            g3 = fmaf(g3, sd.y, sd.x*bv.w);
            D *= sd.y;
            float y = fmaf(g0, cv.x,
                      fmaf(g1, cv.y,
                      fmaf(g2, cv.z, g3*cv.w)));
            y += __shfl_xor_sync(0xffffffffu, y, 8);
            y += __shfl_xor_sync(0xffffffffu, y, 4);
            y += __shfl_xor_sync(0xffffffffu, y, 2);
            y += __shfl_xor_sync(0xffffffffu, y, 1);
            if (li == 0)
                g_yD[(bT + tb + q)*16 + h] = make_float2(y + du, D);
        }
        buf ^= 1;
    }
    int e = ((c*64 + b)*16 + h)*64;
    *(float4*)&g_end[e + 4*li] = make_float4(g0, g1, g2, g3);
}

// ---------------------------------------------------------------------------
// scan2: stitch chunk initial states. One warp per (b,h). All loads issued
// upfront (independent), then a 16-step FMA chain.
// ---------------------------------------------------------------------------
__global__ void scan2_kernel() {
    int chain = blockIdx.x * 8 + (threadIdx.x >> 5);
    int lane  = threadIdx.x & 31;
    int h = chain & 15, b = chain >> 4;

    float P[NC-1], e1[NC-1], e2[NC-1];
    #pragma unroll
    for (int c = 0; c < NC-1; c++) {
        P[c] = g_yD[((size_t)b*T_ + (c+1)*CH - 1)*16 + h].y;
        int e = ((c*64 + b)*16 + h)*64;
        e1[c] = g_end[e + lane];
        e2[c] = g_end[e + lane + 32];
    }
    float g1 = g_g0[h*64 + lane];
    float g2 = g_g0[h*64 + lane + 32];
    int gi = ((0*64 + b)*16 + h)*64;
    g_init[gi + lane]      = g1;
    g_init[gi + lane + 32] = g2;
    #pragma unroll
    for (int c = 1; c < NC; c++) {
        g1 = fmaf(g1, P[c-1], e1[c-1]);
        g2 = fmaf(g2, P[c-1], e2[c-1]);
        gi = ((c*64 + b)*16 + h)*64;
        g_init[gi + lane]      = g1;
        g_init[gi + lane + 32] = g2;
    }
}

// ---------------------------------------------------------------------------
// scan3: correction + head-sum + output. Block per (b,chunk), 8 warps; warp w
// owns 16 timesteps. Chunk initial states for all 16 heads live in registers.
// out[t*64+b] = sum_h [ y_local + D_t * sum_n G_c[h,n] C_t[n] ]
// ---------------------------------------------------------------------------
__global__ void scan3_kernel(float* __restrict__ out, int out_size) {
    int b = blockIdx.x & 63, c = blockIdx.x >> 6;
    int lane = threadIdx.x & 31;
    int w    = threadIdx.x >> 5;

    float gi1[16], gi2[16];
    #pragma unroll
    for (int h = 0; h < 16; h++) {
        int gi = ((c*64 + b)*16 + h)*64;
        gi1[h] = g_init[gi + lane];
        gi2[h] = g_init[gi + lane + 32];
    }

    size_t bT = (size_t)b*T_;
    int tbase = c*CH + w*16;
    #pragma unroll 2
    for (int q = 0; q < 16; q++) {
        int t = tbase + q;
        float c1 = g_C[(bT + t)*64 + lane];
        float c2 = g_C[(bT + t)*64 + lane + 32];
        float2 yD = make_float2(0.f, 0.f);
        if (lane < 16) yD = g_yD[(bT + t)*16 + lane];
        float acc = yD.x;
        #pragma unroll
        for (int h = 0; h < 16; h++) {
            float Dh = __shfl_sync(0xffffffffu, yD.y, h);
            float tl = fmaf(gi2[h], c2, gi1[h]*c1);
            acc = fmaf(Dh, tl, acc);
        }
        acc += __shfl_xor_sync(0xffffffffu, acc, 16);
        acc += __shfl_xor_sync(0xffffffffu, acc, 8);
        acc += __shfl_xor_sync(0xffffffffu, acc, 4);
        acc += __shfl_xor_sync(0xffffffffu, acc, 2);
        acc += __shfl_xor_sync(0xffffffffu, acc, 1);
        if (lane == 0) {
            int idx = t*64 + b;
            for (int j = idx; j < out_size; j += TB) out[j] = acc;
        }
    }
}

// ---------------------------------------------------------------------------
extern "C" void kernel_launch(void* const* d_in, const int* in_sizes, int n_in,
                              void* d_out, int out_size) {
    const float* obs     = (const float*)d_in[0];
    const float* reward  = (const float*)d_in[1];
    const float* W_in    = (const float*)d_in[2];
    const float* W_B     = (const float*)d_in[3];
    const float* W_C     = (const float*)d_in[4];
    const float* W_dt    = (const float*)d_in[5];
    const float* dt_b    = (const float*)d_in[6];
    const float* A_log   = (const float*)d_in[7];
    const float* Dv      = (const float*)d_in[8];
    const float* W_out   = (const float*)d_in[9];
    const float* init    = (const float*)d_in[10];
    float* out = (float*)d_out;

    cudaFuncSetAttribute(proj_kernel,
                         cudaFuncAttributeMaxDynamicSharedMemorySize, PROJ_SMEM);

    prep_kernel<<<8, 256>>>(W_in, W_out, init);
    proj_kernel<<<TB/64, 256, PROJ_SMEM>>>(obs, reward, W_B, W_C,
                                           W_dt, dt_b, A_log, Dv);
    scan1_kernel<<<BK*NC, 256>>>();
    scan2_kernel<<<BK*H_/8, 256>>>();
    scan3_kernel<<<BK*NC, 256>>>(out, out_size);
}